// round 7
// baseline (speedup 1.0000x reference)
#include <cuda_runtime.h>
#include <cuda_bf16.h>
#include <cstdint>
#include <string.h>
#include <math.h>

#define BB 64
#define TT 64
#define AA 64
#define HH 1024

// ---------------- device scratch (allocation-free contract) ----------------
__device__ __align__(16) __nv_bfloat16 g_act_hi[BB * TT * AA];
__device__ __align__(16) __nv_bfloat16 g_act_lo[BB * TT * AA];
__device__ __align__(16) __nv_bfloat16 g_x_hi[BB * TT * 2 * HH];
__device__ __align__(16) __nv_bfloat16 g_x_lo[BB * TT * 2 * HH];
__device__ __align__(16) __nv_bfloat16 g_h_hi[BB * TT * HH];
__device__ __align__(16) __nv_bfloat16 g_h_lo[BB * TT * HH];

// ---------------- helpers ----------------
__device__ __forceinline__ uint32_t smem_u32(const void* p) {
    uint32_t a;
    asm("{ .reg .u64 t; cvta.to.shared.u64 t, %1; cvt.u32.u64 %0, t; }" : "=r"(a) : "l"(p));
    return a;
}

__device__ __forceinline__ void ldsm_x4(uint32_t* r, uint32_t addr) {
    asm volatile("ldmatrix.sync.aligned.m8n8.x4.shared.b16 {%0,%1,%2,%3}, [%4];"
                 : "=r"(r[0]), "=r"(r[1]), "=r"(r[2]), "=r"(r[3]) : "r"(addr));
}
__device__ __forceinline__ void ldsm_x4t(uint32_t* r, uint32_t addr) {
    asm volatile("ldmatrix.sync.aligned.m8n8.x4.trans.shared.b16 {%0,%1,%2,%3}, [%4];"
                 : "=r"(r[0]), "=r"(r[1]), "=r"(r[2]), "=r"(r[3]) : "r"(addr));
}
__device__ __forceinline__ void mma_bf16(float* d, const uint32_t* a, const uint32_t* bfr) {
    asm volatile("mma.sync.aligned.m16n8k16.row.col.f32.bf16.bf16.f32 "
                 "{%0,%1,%2,%3}, {%4,%5,%6,%7}, {%8,%9}, {%0,%1,%2,%3};"
                 : "+f"(d[0]), "+f"(d[1]), "+f"(d[2]), "+f"(d[3])
                 : "r"(a[0]), "r"(a[1]), "r"(a[2]), "r"(a[3]), "r"(bfr[0]), "r"(bfr[1]));
}

__device__ __forceinline__ uint32_t bits2(__nv_bfloat162 v) {
    uint32_t w; memcpy(&w, &v, 4); return w;
}
__device__ __forceinline__ void split2(float v, __nv_bfloat16& h, __nv_bfloat16& l) {
    h = __float2bfloat16(v);
    l = __float2bfloat16(v - __bfloat162float(h));
}
// 8 consecutive floats -> hi uint4 + lo uint4 (bf16 pairs)
__device__ __forceinline__ void cvt8(float4 u, float4 v, uint4& hi, uint4& lo) {
    float f[8] = {u.x, u.y, u.z, u.w, v.x, v.y, v.z, v.w};
    uint32_t h[4], l[4];
    #pragma unroll
    for (int i = 0; i < 4; i++) {
        float a = f[2 * i], b = f[2 * i + 1];
        __nv_bfloat162 hh = __floats2bfloat162_rn(a, b);
        float ra = a - __bfloat162float(__low2bfloat16(hh));
        float rb = b - __bfloat162float(__high2bfloat16(hh));
        __nv_bfloat162 ll = __floats2bfloat162_rn(ra, rb);
        h[i] = bits2(hh); l[i] = bits2(ll);
    }
    hi = make_uint4(h[0], h[1], h[2], h[3]);
    lo = make_uint4(l[0], l[1], l[2], l[3]);
}

// ---------------- prep kernels ----------------
__global__ void prep_act_kernel(const float* __restrict__ actions) {
    const int b = blockIdx.x;
    for (int i = threadIdx.x; i < TT * AA; i += blockDim.x) {
        float v = actions[b * TT * AA + i];
        __nv_bfloat16 h, l; split2(v, h, l);
        g_act_hi[b * TT * AA + i] = h;
        g_act_lo[b * TT * AA + i] = l;
    }
}

__global__ void tau_fill_kernel(const int* __restrict__ timesteps) {
    __shared__ uint32_t hi2[512], lo2[512];
    const int b = blockIdx.x;
    const float t = (float)timesteps[b];
    const float kexp = 9.210340371976184f / 512.0f;
    for (int p = threadIdx.x; p < 512; p += blockDim.x) {
        int j0 = 2 * p, j1 = 2 * p + 1;
        int i0 = (j0 < 512) ? j0 : (j0 - 512);
        int i1 = (j1 < 512) ? j1 : (j1 - 512);
        float f0 = t * expf(-(float)i0 * kexp);
        float f1 = t * expf(-(float)i1 * kexp);
        float v0 = (j0 < 512) ? sinf(f0) : cosf(f0);
        float v1 = (j1 < 512) ? sinf(f1) : cosf(f1);
        __nv_bfloat16 h0, l0, h1, l1; split2(v0, h0, l0); split2(v1, h1, l1);
        hi2[p] = (uint32_t)__bfloat16_as_ushort(h0) | ((uint32_t)__bfloat16_as_ushort(h1) << 16);
        lo2[p] = (uint32_t)__bfloat16_as_ushort(l0) | ((uint32_t)__bfloat16_as_ushort(l1) << 16);
    }
    __syncthreads();
    for (int tt = 0; tt < TT; tt++) {
        uint32_t* dh = (uint32_t*)(g_x_hi + ((size_t)(b * TT + tt) * 2 * HH + HH));
        uint32_t* dl = (uint32_t*)(g_x_lo + ((size_t)(b * TT + tt) * 2 * HH + HH));
        for (int i = threadIdx.x; i < 512; i += blockDim.x) {
            dh[i] = hi2[i];
            dl[i] = lo2[i];
        }
    }
}

// ---------------- main GEMM: mma.sync bf16, 3-pass hi/lo split ----------------
// CTA: 128 thr (4 warps 1Mx4N). Tile M=64 tokens x N=256 feats. K-stage 32.
// Warp tile 64x64 (mt=4, n8=8)  ->  MMA:LDSM ratio 6:1.
// Stage smem (40KB): A 64x128B (4 hi + 4 lo 16B chunks), Bhi 32x512B, Blo 32x512B.
// Swizzle: 16B-chunk ^ (row & 7). Two stages (80KB dynamic).
// mode 0: K=64   X=g_act -> g_x[:, :1024] (+bias)
// mode 1: K=2048 X=g_x   -> g_h (swish(+bias))
// mode 2: K=1024 X=g_h   -> fp32 out (+bias)

#define STG 40960
#define OFF_BH 8192
#define OFF_BL 24576
#define SMEM_TOT (2 * STG)

__global__ __launch_bounds__(128, 2) void gemm_kernel(
    const float* __restrict__ W, const float* __restrict__ bias,
    const int* __restrict__ cat_ids, float* __restrict__ outf, int mode)
{
    extern __shared__ char smem[];
    const int tid = threadIdx.x;
    const int wid = tid >> 5, lane = tid & 31;
    const int b = blockIdx.y;
    const int n0 = blockIdx.x * 256;
    const int c = cat_ids[b];

    int KTOT, ldb;
    const __nv_bfloat16 *Xhi, *Xlo;
    if (mode == 0)      { KTOT = 64;   ldb = 64;   Xhi = g_act_hi; Xlo = g_act_lo; }
    else if (mode == 1) { KTOT = 2048; ldb = 2048; Xhi = g_x_hi;   Xlo = g_x_lo; }
    else                { KTOT = 1024; ldb = 1024; Xhi = g_h_hi;   Xlo = g_h_lo; }

    const float* Wc = W + (size_t)c * KTOT * HH;
    const uint32_t sbase = smem_u32(smem);

    // ---- staging maps ----
    // A: thread -> (row, 16-elem part).  128 thr cover 64 rows x 32 k.
    const int rowA = tid >> 1, partA = tid & 1;
    const __nv_bfloat16* gAh = Xhi + (size_t)(b * TT + rowA) * ldb + partA * 16;
    const __nv_bfloat16* gAl = Xlo + (size_t)(b * TT + rowA) * ldb + partA * 16;
    // W: iteration j covers rows j*4 + wid, chunk = lane (8 fp32 = 1 bf16 16B chunk).
    const float* gW = Wc + (size_t)wid * HH + n0 + lane * 8;

    float acc[4][8][4];
    #pragma unroll
    for (int i = 0; i < 4; i++)
        #pragma unroll
        for (int j = 0; j < 8; j++)
            #pragma unroll
            for (int q = 0; q < 4; q++) acc[i][j][q] = 0.0f;

    const int nst = KTOT >> 5;

    float4 wv0[8], wv1[8];

    auto ldgW = [&](int k0, int j0, float4* wv) {
        #pragma unroll
        for (int q = 0; q < 4; q++) {
            const float* p = gW + (size_t)(k0 + (j0 + q) * 4) * HH;
            wv[2 * q]     = *(const float4*)p;
            wv[2 * q + 1] = *(const float4*)(p + 4);
        }
    };
    auto stsW = [&](int j0, int buf, const float4* wv) {
        char* st = smem + buf * STG;
        #pragma unroll
        for (int q = 0; q < 4; q++) {
            const int row = (j0 + q) * 4 + wid;
            uint4 hi, lo;
            cvt8(wv[2 * q], wv[2 * q + 1], hi, lo);
            const uint32_t a = (uint32_t)row * 512 + (uint32_t)((lane ^ (row & 7)) * 16);
            *(uint4*)(st + OFF_BH + a) = hi;
            *(uint4*)(st + OFF_BL + a) = lo;
        }
    };
    auto ldg_sts_A = [&](int k0, int buf) {
        uint4 h0 = *(const uint4*)(gAh + k0);
        uint4 h1 = *(const uint4*)(gAh + k0 + 8);
        uint4 l0 = *(const uint4*)(gAl + k0);
        uint4 l1 = *(const uint4*)(gAl + k0 + 8);
        char* st = smem + buf * STG;
        const uint32_t ra = (uint32_t)rowA * 128;
        const int c0 = partA * 2, c1 = partA * 2 + 1;
        *(uint4*)(st + ra + (uint32_t)((c0       ^ (rowA & 7)) * 16)) = h0;
        *(uint4*)(st + ra + (uint32_t)((c1       ^ (rowA & 7)) * 16)) = h1;
        *(uint4*)(st + ra + (uint32_t)(((c0 + 4) ^ (rowA & 7)) * 16)) = l0;
        *(uint4*)(st + ra + (uint32_t)(((c1 + 4) ^ (rowA & 7)) * 16)) = l1;
    };

    const int wn = wid;               // 4 warps tile N: warp covers cols wn*64..wn*64+63
    const int lr = lane & 15, lc = lane >> 4;

    auto compute_kk = [&](int buf, int kk) {
        const uint32_t Ab = sbase + buf * STG;
        const uint32_t Bh = Ab + OFF_BH;
        const uint32_t Bl = Ab + OFF_BL;
        uint32_t ah[4][4], al[4][4];
        #pragma unroll
        for (int mt = 0; mt < 4; mt++) {
            const int r = mt * 16 + lr;
            const int cb = kk * 2 + lc;
            ldsm_x4(ah[mt], Ab + (uint32_t)r * 128 + (uint32_t)((cb       ^ (r & 7)) * 16));
            ldsm_x4(al[mt], Ab + (uint32_t)r * 128 + (uint32_t)(((cb + 4) ^ (r & 7)) * 16));
        }
        const int kr = kk * 16 + lr;
        #pragma unroll
        for (int gh = 0; gh < 2; gh++) {
            uint32_t bh[2][4], bl[2][4];
            #pragma unroll
            for (int g2 = 0; g2 < 2; g2++) {
                const int ch = wn * 8 + (gh * 2 + g2) * 2 + lc;
                const uint32_t ba = (uint32_t)kr * 512 + (uint32_t)((ch ^ (kr & 7)) * 16);
                ldsm_x4t(bh[g2], Bh + ba);
                ldsm_x4t(bl[g2], Bl + ba);
            }
            #pragma unroll
            for (int mt = 0; mt < 4; mt++)
                #pragma unroll
                for (int n8l = 0; n8l < 4; n8l++) {
                    const int n8 = gh * 4 + n8l;
                    const int g2 = n8l >> 1, hf = (n8l & 1) * 2;
                    mma_bf16(acc[mt][n8], ah[mt], &bh[g2][hf]);
                    mma_bf16(acc[mt][n8], al[mt], &bh[g2][hf]);
                    mma_bf16(acc[mt][n8], ah[mt], &bl[g2][hf]);
                }
        }
    };

    // ---- prologue: fill stage 0 ----
    ldgW(0, 0, wv0);
    ldgW(0, 4, wv1);
    ldg_sts_A(0, 0);
    stsW(0, 0, wv0);
    stsW(4, 0, wv1);
    __syncthreads();

    // ---- main loop: compute s, interleave fill of s+1 ----
    for (int s = 0; s < nst; s++) {
        const int buf = s & 1, nbuf = (s + 1) & 1;
        const int nk = (s + 1) << 5;
        const bool more = (s + 1 < nst);
        if (more) { ldgW(nk, 0, wv0); ldg_sts_A(nk, nbuf); }
        compute_kk(buf, 0);
        if (more) { stsW(0, nbuf, wv0); ldgW(nk, 4, wv1); }
        compute_kk(buf, 1);
        if (more) { stsW(4, nbuf, wv1); }
        __syncthreads();
    }

    // ---- epilogue ----
    const int r4 = lane >> 2, c2 = (lane & 3) * 2;
    const float* bp = bias + (size_t)c * HH + n0 + wn * 64;

    if (mode == 2) {
        #pragma unroll
        for (int mt = 0; mt < 4; mt++)
            #pragma unroll
            for (int n8 = 0; n8 < 8; n8++) {
                const int row = mt * 16 + r4;
                const int col = wn * 64 + n8 * 8 + c2;
                const float b0 = bp[n8 * 8 + c2], b1 = bp[n8 * 8 + c2 + 1];
                float* o0 = outf + (size_t)(b * TT + row) * HH + n0 + col;
                float* o1 = outf + (size_t)(b * TT + row + 8) * HH + n0 + col;
                *(float2*)o0 = make_float2(acc[mt][n8][0] + b0, acc[mt][n8][1] + b1);
                *(float2*)o1 = make_float2(acc[mt][n8][2] + b0, acc[mt][n8][3] + b1);
            }
    } else {
        const int ldo = (mode == 0) ? 2 * HH : HH;
        __nv_bfloat16* Ohi = (mode == 0) ? g_x_hi : g_h_hi;
        __nv_bfloat16* Olo = (mode == 0) ? g_x_lo : g_h_lo;
        #pragma unroll
        for (int mt = 0; mt < 4; mt++)
            #pragma unroll
            for (int n8 = 0; n8 < 8; n8++) {
                const int col = wn * 64 + n8 * 8 + c2;
                const float b0 = bp[n8 * 8 + c2], b1 = bp[n8 * 8 + c2 + 1];
                #pragma unroll
                for (int hrow = 0; hrow < 2; hrow++) {
                    const int row = mt * 16 + r4 + hrow * 8;
                    float va = acc[mt][n8][hrow * 2 + 0] + b0;
                    float vb = acc[mt][n8][hrow * 2 + 1] + b1;
                    if (mode == 1) {
                        va = va / (1.0f + expf(-va));
                        vb = vb / (1.0f + expf(-vb));
                    }
                    __nv_bfloat162 hh = __floats2bfloat162_rn(va, vb);
                    float ra = va - __bfloat162float(__low2bfloat16(hh));
                    float rb = vb - __bfloat162float(__high2bfloat16(hh));
                    __nv_bfloat162 ll = __floats2bfloat162_rn(ra, rb);
                    const size_t o = (size_t)(b * TT + row) * ldo + n0 + col;
                    *(uint32_t*)(Ohi + o) = bits2(hh);
                    *(uint32_t*)(Olo + o) = bits2(ll);
                }
            }
    }
}

// ---------------- harness entry ----------------
extern "C" void kernel_launch(void* const* d_in, const int* in_sizes, int n_in,
                              void* d_out, int out_size)
{
    const float* actions   = (const float*)d_in[0];
    const int*   timesteps = (const int*)  d_in[1];
    const int*   cat_ids   = (const int*)  d_in[2];
    const float* W1        = (const float*)d_in[3];
    const float* b1        = (const float*)d_in[4];
    const float* W2        = (const float*)d_in[5];
    const float* b2        = (const float*)d_in[6];
    const float* W3        = (const float*)d_in[7];
    const float* b3        = (const float*)d_in[8];
    float* out = (float*)d_out;

    cudaFuncSetAttribute(gemm_kernel,
                         cudaFuncAttributeMaxDynamicSharedMemorySize, SMEM_TOT);

    prep_act_kernel<<<BB, 256>>>(actions);
    tau_fill_kernel<<<BB, 256>>>(timesteps);

    dim3 grid(HH / 256, BB);   // 4 feature-tiles x 64 batches
    gemm_kernel<<<grid, 128, SMEM_TOT>>>(W1, b1, cat_ids, nullptr, 0);
    gemm_kernel<<<grid, 128, SMEM_TOT>>>(W2, b2, cat_ids, nullptr, 1);
    gemm_kernel<<<grid, 128, SMEM_TOT>>>(W3, b3, cat_ids, out, 2);
}